// round 15
// baseline (speedup 1.0000x reference)
#include <cuda_runtime.h>

#define NFSZ 1001
#define HSZ   256
#define BSZ   64
#define FD    128
#define INCH  16
#define G4    1024   // 4*H
#define INS0  144    // FD + INCH

// device-global scratch (allocation-free rule)
__device__ float g_Gf[NFSZ * G4];                // pre-scaled f-side gate pre-acts
__device__ unsigned long long g_mb[BSZ * 1024];  // layer0->layer1 mailbox {tag,val}

__device__ __forceinline__ float ex2f(float x) {
    float y; asm("ex2.approx.f32 %0, %1;" : "=f"(y) : "f"(x)); return y;
}
__device__ __forceinline__ float rcpf(float x) {
    float y; asm("rcp.approx.f32 %0, %1;" : "=f"(y) : "f"(x)); return y;
}
__device__ __forceinline__ float negabsf(float x) {
    return __int_as_float(__float_as_int(x) | 0x80000000);
}
__device__ __forceinline__ unsigned long long ldv64(const unsigned long long* p) {
    unsigned long long v;
    asm volatile("ld.volatile.global.b64 %0, [%1];" : "=l"(v) : "l"(p));
    return v;
}
__device__ __forceinline__ void stv64(unsigned long long* p, unsigned long long v) {
    asm volatile("st.volatile.global.b64 [%0], %1;" :: "l"(p), "l"(v) : "memory");
}
__device__ __forceinline__ unsigned long long packtv(unsigned tag, float val) {
    return ((unsigned long long)tag << 32) | (unsigned)__float_as_int(val);
}
__device__ __forceinline__ float valof(unsigned long long v) {
    return __int_as_float((int)(unsigned)v);
}

#define L2E   1.4426950408889634f
#define NL2E2 -2.8853900817779268f

// ---------------- precompute: Gf = scale * (f @ Wf^T)  (layout [t][gate*256+u]) ----------------
__global__ __launch_bounds__(256) void gf_kernel(const float* __restrict__ f,
                                                 const float* __restrict__ Wih0) {
    __shared__ float Wc[256][33];
    __shared__ float fs[8][32];
    const int tid = threadIdx.x;
    const int t0  = blockIdx.x * 8;
    const int gb  = blockIdx.y * 256;

    float acc[8] = {0.f,0.f,0.f,0.f,0.f,0.f,0.f,0.f};
    for (int kc = 0; kc < FD; kc += 32) {
        #pragma unroll
        for (int i = 0; i < 32; i++) {
            int e  = i * 256 + tid;
            int gl = e >> 5, kk = e & 31;
            Wc[gl][kk] = Wih0[(gb + gl) * INS0 + kc + kk];
        }
        {
            int tt = tid >> 5, kk = tid & 31;
            int t = t0 + tt;
            fs[tt][kk] = (t < NFSZ) ? f[t * FD + kc + kk] : 0.f;
        }
        __syncthreads();
        #pragma unroll 8
        for (int kk = 0; kk < 32; kk++) {
            float w = Wc[tid][kk];
            #pragma unroll
            for (int tt = 0; tt < 8; tt++) acc[tt] = fmaf(fs[tt][kk], w, acc[tt]);
        }
        __syncthreads();
    }
    float scale = (blockIdx.y == 2) ? NL2E2 : -L2E;
    #pragma unroll
    for (int tt = 0; tt < 8; tt++) {
        int t = t0 + tt;
        if (t < NFSZ) g_Gf[t * G4 + gb + tid] = acc[tt] * scale;
    }
}

// ---------------- main LSTM: 2 CTAs per batch (R12-proven skeleton) ----------------
// blk even -> role A (layer0: 256 thr, 1 unit/thread, __syncthreads lockstep)
// blk odd  -> role B (layers 1+2 as two 128-thr warpgroups, shared __syncthreads)
// A->B: tagged gmem mailbox (3-tick skew, prefetched). B: layer1->2 parity scalar.
// Activation: 7-MUFU independent-chain form. NEW: x2 unrolled ticks; role B uses
// full 5-level shfl -> 4 partials/layer (shorter gather).

__global__ __launch_bounds__(256, 1) void lstm_kernel(
    const float* __restrict__ x,
    const float* __restrict__ Wih0, const float* __restrict__ Whh0,
    const float* __restrict__ bih0, const float* __restrict__ bhh0,
    const float* __restrict__ Whr0,
    const float* __restrict__ Wih1, const float* __restrict__ Whh1,
    const float* __restrict__ bih1, const float* __restrict__ bhh1,
    const float* __restrict__ Whr1,
    const float* __restrict__ Wih2, const float* __restrict__ Whh2,
    const float* __restrict__ bih2, const float* __restrict__ bhh2,
    const float* __restrict__ Whr2,
    float* __restrict__ out)
{
    __shared__ __align__(16) float partA[2][8];     // role A: one partial per warp
    __shared__ __align__(16) float partB[2][2][4];  // role B: [parity][layer][warp]
    __shared__ float fwdB[2];                       // layer1 -> layer2 scalar

    const int b    = blockIdx.x >> 1;
    const int role = blockIdx.x & 1;
    const int tid  = threadIdx.x;

    if (role == 0) {
        // ================= ROLE A : layer 0, 1 unit per thread =================
        const int u    = tid;
        const int warp = tid >> 5;
        const int lane = tid & 31;

        float whh_s[4], base_s[4];
        #pragma unroll
        for (int g = 0; g < 4; g++) {
            int idx  = g * HSZ + u;
            float sc = (g == 2) ? NL2E2 : -L2E;
            whh_s[g] = Whh0[idx] * sc;
            float acc = bih0[idx] + bhh0[idx];
            #pragma unroll
            for (int kk = 0; kk < INCH; kk++)
                acc = fmaf(x[b * INCH + kk], Wih0[idx * INS0 + FD + kk], acc);
            base_s[g] = acc * sc;
        }
        const float whr = Whr0[u];
        float c = 0.f;

        if (tid < 8)  { partA[0][tid] = 0.f; partA[1][tid] = 0.f; }
        __syncthreads();

        float gA[4], gB[4];
        #pragma unroll
        for (int g = 0; g < 4; g++) gA[g] = g_Gf[g * HSZ + u] + base_s[g];

        unsigned long long* mb = &g_mb[b * 1024];

#define ATICK(KT, GC, GN, PAR)                                                  \
        {                                                                       \
            const int k_ = (KT);                                                \
            if (k_ + 1 <= NFSZ - 1) {                                           \
                const float* gp = &g_Gf[(k_ + 1) * G4 + u];                     \
                _Pragma("unroll")                                               \
                for (int g = 0; g < 4; g++) GN[g] = gp[g * HSZ] + base_s[g];    \
            }                                                                   \
            float4 p0 = *(const float4*)&partA[(PAR) ^ 1][0];                   \
            float4 p1 = *(const float4*)&partA[(PAR) ^ 1][4];                   \
            float h_prev = ((p0.x + p0.y) + (p0.z + p0.w))                      \
                         + ((p1.x + p1.y) + (p1.z + p1.w));                     \
            if (k_ >= 1 && tid == 0)                                            \
                stv64(&mb[k_ - 1], packtv((unsigned)k_, h_prev));               \
            if (k_ <= NFSZ - 1) {                                               \
                float pre0 = fmaf(whh_s[0], h_prev, GC[0]);                     \
                float pre1 = fmaf(whh_s[1], h_prev, GC[1]);                     \
                float pre2 = fmaf(whh_s[2], h_prev, GC[2]);                     \
                float pre3 = fmaf(whh_s[3], h_prev, GC[3]);                     \
                float ei = ex2f(pre0), ef = ex2f(pre1), eo = ex2f(pre3);        \
                float eg = ex2f(negabsf(pre2));                                 \
                float pi = 1.f + ei, pf = 1.f + ef, pg = 1.f + eg;              \
                float PP = pi * pg;                                             \
                float R  = rcpf(PP * pf);                                       \
                float tnum = fmaf(eg, -pf, pf);                                 \
                float num  = fmaf(c, PP, copysignf(tnum, -pre2));               \
                c = num * R;                                                    \
                float ec = ex2f(NL2E2 * fabsf(c));                              \
                float hm = fmaf(ec, -1.f, 1.f) * rcpf((1.f + eo) * (1.f + ec)); \
                float hr = copysignf(hm, c);                                    \
                float partial = hr * whr;                                       \
                partial += __shfl_xor_sync(0xffffffffu, partial, 16);           \
                partial += __shfl_xor_sync(0xffffffffu, partial, 8);            \
                partial += __shfl_xor_sync(0xffffffffu, partial, 4);            \
                partial += __shfl_xor_sync(0xffffffffu, partial, 2);            \
                partial += __shfl_xor_sync(0xffffffffu, partial, 1);            \
                if (lane == 0) partA[PAR][warp] = partial;                      \
            }                                                                   \
            __syncthreads();                                                    \
        }

        for (int k = 0; k <= NFSZ - 1; k += 2) {   // 1002 ticks: (0,1)..(1000,1001)
            ATICK(k,     gA, gB, 0)
            ATICK(k + 1, gB, gA, 1)
        }
#undef ATICK
    } else {
        // ============ ROLE B : layers 1 (wg0, t=k-3) + 2 (wg1, t=k-5) ============
        const int wg   = tid >> 7;          // 0 -> layer1, 1 -> layer2
        const int wtid = tid & 127;
        const int warp = wtid >> 5;
        const int lane = wtid & 31;
        const int u0   = wtid * 2;

        const float* Whh = wg ? Whh2 : Whh1;
        const float* Wih = wg ? Wih2 : Wih1;
        const float* bih = wg ? bih2 : bih1;
        const float* bhh = wg ? bhh2 : bhh1;
        const float* Whr = wg ? Whr2 : Whr1;
        const int skew = wg ? 5 : 3;

        float whh_s[8], base_s[8], wih_s[8];
        #pragma unroll
        for (int j = 0; j < 8; j++) {
            int gate = j >> 1;
            int idx  = gate * HSZ + u0 + (j & 1);
            float sc = (gate == 2) ? NL2E2 : -L2E;
            whh_s[j]  = Whh[idx] * sc;
            base_s[j] = (bih[idx] + bhh[idx]) * sc;
            wih_s[j]  = Wih[idx] * sc;
        }
        const float w0 = Whr[u0], w1 = Whr[u0 + 1];
        float cs0 = 0.f, cs1 = 0.f;

        if (wtid < 4) { partB[0][wg][wtid] = 0.f; partB[1][wg][wtid] = 0.f; }
        if (tid < 2)  fwdB[tid] = 0.f;
        __syncthreads();

        unsigned long long* mbin = &g_mb[b * 1024];
        unsigned long long mv = 0;   // prefetched mailbox word (layer1 only)
        float* outp = out + b * NFSZ;

#define BTICK(KT, PAR)                                                          \
        {                                                                       \
            const int k_ = (KT);                                                \
            const int t = k_ - skew;                                            \
            const bool active = (t >= 0) && (t < NFSZ);                         \
            float4 p = *(const float4*)partB[(PAR) ^ 1][wg];                    \
            float h_prev = (p.x + p.y) + (p.z + p.w);                           \
            float u_in = 0.f;                                                   \
            if (wg == 0) {                                                      \
                if (active) {                                                   \
                    unsigned exp_flag = (unsigned)(t + 1);                      \
                    while ((unsigned)(mv >> 32) != exp_flag)                    \
                        mv = ldv64(&mbin[t]);                                   \
                    u_in = valof(mv);                                           \
                }                                                               \
                if (wtid == 0) fwdB[PAR] = h_prev;                              \
            } else {                                                            \
                u_in = fwdB[(PAR) ^ 1];                                         \
                if (wtid == 0 && k_ >= 6 && k_ <= NFSZ + 5)                     \
                    outp[k_ - 6] = h_prev;                                      \
            }                                                                   \
            if (active) {                                                       \
                float pre[8];                                                   \
                _Pragma("unroll")                                               \
                for (int j = 0; j < 8; j++)                                     \
                    pre[j] = fmaf(whh_s[j], h_prev,                             \
                                  fmaf(wih_s[j], u_in, base_s[j]));             \
                float partial = 0.f;                                            \
                _Pragma("unroll")                                               \
                for (int m = 0; m < 2; m++) {                                   \
                    float ei = ex2f(pre[m]);                                    \
                    float ef = ex2f(pre[2 + m]);                                \
                    float gs = pre[4 + m];                                      \
                    float eg = ex2f(negabsf(gs));                               \
                    float eo = ex2f(pre[6 + m]);                                \
                    float pi = 1.f + ei, pf = 1.f + ef, pg = 1.f + eg;          \
                    float PP = pi * pg;                                         \
                    float R  = rcpf(PP * pf);                                   \
                    float tnum = fmaf(eg, -pf, pf);                             \
                    float c = (m == 0) ? cs0 : cs1;                             \
                    float num = fmaf(c, PP, copysignf(tnum, -gs));              \
                    c = num * R;                                                \
                    float ec = ex2f(NL2E2 * fabsf(c));                          \
                    float hm = fmaf(ec, -1.f, 1.f)                              \
                             * rcpf((1.f + eo) * (1.f + ec));                   \
                    float hr = copysignf(hm, c);                                \
                    if (m == 0) { cs0 = c; partial = fmaf(hr, w0, partial); }   \
                    else        { cs1 = c; partial = fmaf(hr, w1, partial); }   \
                }                                                               \
                partial += __shfl_xor_sync(0xffffffffu, partial, 16);           \
                partial += __shfl_xor_sync(0xffffffffu, partial, 8);            \
                partial += __shfl_xor_sync(0xffffffffu, partial, 4);            \
                partial += __shfl_xor_sync(0xffffffffu, partial, 2);            \
                partial += __shfl_xor_sync(0xffffffffu, partial, 1);            \
                if (lane == 0) partB[PAR][wg][warp] = partial;                  \
            }                                                                   \
            if (wg == 0) {                                                      \
                int tn = t + 1;                                                 \
                if (tn >= 0 && tn < NFSZ) mv = ldv64(&mbin[tn]);                \
            }                                                                   \
            __syncthreads();                                                    \
        }

        for (int k = 0; k < NFSZ + 7; k += 2) {   // 1008 ticks: (0,1)..(1006,1007)
            BTICK(k,     0)
            BTICK(k + 1, 1)
        }
#undef BTICK
    }
}

// ---------------- launch ----------------

extern "C" void kernel_launch(void* const* d_in, const int* in_sizes, int n_in,
                              void* d_out, int out_size) {
    const float* x    = (const float*)d_in[0];
    const float* f    = (const float*)d_in[1];
    const float* Wih0 = (const float*)d_in[2];
    const float* Whh0 = (const float*)d_in[3];
    const float* bih0 = (const float*)d_in[4];
    const float* bhh0 = (const float*)d_in[5];
    const float* Whr0 = (const float*)d_in[6];
    const float* Wih1 = (const float*)d_in[7];
    const float* Whh1 = (const float*)d_in[8];
    const float* bih1 = (const float*)d_in[9];
    const float* bhh1 = (const float*)d_in[10];
    const float* Whr1 = (const float*)d_in[11];
    const float* Wih2 = (const float*)d_in[12];
    const float* Whh2 = (const float*)d_in[13];
    const float* bih2 = (const float*)d_in[14];
    const float* bhh2 = (const float*)d_in[15];
    const float* Whr2 = (const float*)d_in[16];

    gf_kernel<<<dim3(126, 4), 256>>>(f, Wih0);
    lstm_kernel<<<2 * BSZ, 256>>>(x,
                                  Wih0, Whh0, bih0, bhh0, Whr0,
                                  Wih1, Whh1, bih1, bhh1, Whr1,
                                  Wih2, Whh2, bih2, bhh2, Whr2,
                                  (float*)d_out);
}